// round 2
// baseline (speedup 1.0000x reference)
#include <cuda_runtime.h>
#include <math.h>

#define MAXN 400000
#define MAXB 10000

// Scratch (static device globals; no allocations)
__device__ float g_w[MAXN];
__device__ float g_ew[MAXN];
__device__ float g_anorm[MAXB];
__device__ float g_bmax[(MAXN + 7) / 8];
__device__ float g_A[256];   // A0[0:128], A1[128:256]
__device__ float g_s[4];     // [0]=s0, [1]=s1, [2]=wmax, [3]=S

// shifted softplus: softplus(x) - ln(2)
__device__ __forceinline__ float sspf(float x) {
    float ax = fabsf(x);
    float t = __expf(-ax);
    return fmaxf(x, 0.f) + __logf(1.f + t) - 0.69314718055994531f;
}

// ---------------------------------------------------------------------------
// K0: A0[j] = sum_f Wq[f,j]*Wk[f,0]; A1[j] = sum_f Wq[f,j]*Wk[f,1];
//     s0 = bq . Wk[:,0]; s1 = bq . Wk[:,1]
// ---------------------------------------------------------------------------
__global__ void k_prep(const float* __restrict__ Wq, const float* __restrict__ bq,
                       const float* __restrict__ Wk) {
    int j = threadIdx.x;  // 0..127
    float a0 = 0.f, a1 = 0.f;
    for (int f = 0; f < 128; f++) {
        float wq = Wq[f * 128 + j];
        a0 += wq * Wk[2 * f];
        a1 += wq * Wk[2 * f + 1];
    }
    g_A[j] = a0;
    g_A[128 + j] = a1;

    __shared__ float sb[128];
    sb[j] = bq[j] * Wk[2 * j];
    __syncthreads();
    for (int o = 64; o > 0; o >>= 1) {
        if (j < o) sb[j] += sb[j + o];
        __syncthreads();
    }
    if (j == 0) g_s[0] = sb[0];
    __syncthreads();
    sb[j] = bq[j] * Wk[2 * j + 1];
    __syncthreads();
    for (int o = 64; o > 0; o >>= 1) {
        if (j < o) sb[j] += sb[j + o];
        __syncthreads();
    }
    if (j == 0) g_s[1] = sb[0];
}

// ---------------------------------------------------------------------------
// K1: w[i] = (x_i . (en0*A0 + en1*A1) + en0*s0 + en1*s1) / sqrt(128)
//     one warp per row; also per-block max -> g_bmax
// ---------------------------------------------------------------------------
__global__ void k_w(const float* __restrict__ x, const float* __restrict__ ef,
                    const int* __restrict__ idx, int N) {
    __shared__ float A0s[128], A1s[128];
    __shared__ float wms[8];
    int t = threadIdx.x;  // 256 threads, 8 warps
    if (t < 128) A0s[t] = g_A[t];
    else A1s[t - 128] = g_A[t];
    __syncthreads();

    int warp = t >> 5, lane = t & 31;
    int i = blockIdx.x * 8 + warp;
    float wv = -INFINITY;
    if (i < N) {
        int b = idx[i];
        float v = ef[b];
        float e0 = fmaxf(v, 0.f), e1 = fmaxf(-v, 0.f);
        float en0 = e0 / fmaxf(e0, 1.f), en1 = e1 / fmaxf(e1, 1.f);
        float4 xv = ((const float4*)(x + (size_t)i * 128))[lane];
        int j = lane * 4;
        float dot = xv.x * (en0 * A0s[j] + en1 * A1s[j]) +
                    xv.y * (en0 * A0s[j + 1] + en1 * A1s[j + 1]) +
                    xv.z * (en0 * A0s[j + 2] + en1 * A1s[j + 2]) +
                    xv.w * (en0 * A0s[j + 3] + en1 * A1s[j + 3]);
#pragma unroll
        for (int o = 16; o > 0; o >>= 1) dot += __shfl_xor_sync(0xffffffffu, dot, o);
        wv = (dot + en0 * g_s[0] + en1 * g_s[1]) * 0.08838834764831845f;  // 1/sqrt(128)
        if (lane == 0) g_w[i] = wv;
    }
    if (lane == 0) wms[warp] = wv;
    __syncthreads();
    if (t == 0) {
        float m = wms[0];
#pragma unroll
        for (int k = 1; k < 8; k++) m = fmaxf(m, wms[k]);
        g_bmax[blockIdx.x] = m;
    }
}

// ---------------------------------------------------------------------------
// K2: global max of block maxima -> g_s[2]   (single block, deterministic)
// ---------------------------------------------------------------------------
__global__ void k_max(int nb) {
    __shared__ float sd[1024];
    float m = -INFINITY;
    for (int i = threadIdx.x; i < nb; i += 1024) m = fmaxf(m, g_bmax[i]);
    sd[threadIdx.x] = m;
    __syncthreads();
    for (int o = 512; o > 0; o >>= 1) {
        if (threadIdx.x < o) sd[threadIdx.x] = fmaxf(sd[threadIdx.x], sd[threadIdx.x + o]);
        __syncthreads();
    }
    if (threadIdx.x == 0) g_s[2] = sd[0];
}

// ---------------------------------------------------------------------------
// K3: ew[i] = exp(w[i] - wmax)
// ---------------------------------------------------------------------------
__global__ void k_exp(int N) {
    int i = blockIdx.x * blockDim.x + threadIdx.x;
    if (i < N) g_ew[i] = expf(g_w[i] - g_s[2]);
}

// ---------------------------------------------------------------------------
// K4: per-molecule segment sums via binary search (idx sorted), deterministic.
//     one warp per molecule.
// ---------------------------------------------------------------------------
__device__ __forceinline__ int lbound(const int* __restrict__ a, int n, int v) {
    int lo = 0, hi = n;
    while (lo < hi) {
        int m = (lo + hi) >> 1;
        if (a[m] < v) lo = m + 1;
        else hi = m;
    }
    return lo;
}

__global__ void k_anorm(const int* __restrict__ idx, int N, int B) {
    int gw = (blockIdx.x * blockDim.x + threadIdx.x) >> 5;
    int lane = threadIdx.x & 31;
    if (gw >= B) return;
    int lo = lbound(idx, N, gw);
    int hi = lbound(idx, N, gw + 1);
    float s = 0.f;
    for (int i = lo + lane; i < hi; i += 32) s += g_ew[i];
#pragma unroll
    for (int o = 16; o > 0; o >>= 1) s += __shfl_xor_sync(0xffffffffu, s, o);
    if (lane == 0) g_anorm[gw] = s;
}

// ---------------------------------------------------------------------------
// K5: S = sum_b anorm_raw[b]   (single block, deterministic)
// ---------------------------------------------------------------------------
__global__ void k_sum(int B) {
    __shared__ float sd[1024];
    float s = 0.f;
    for (int i = threadIdx.x; i < B; i += 1024) s += g_anorm[i];
    sd[threadIdx.x] = s;
    __syncthreads();
    for (int o = 512; o > 0; o >>= 1) {
        if (threadIdx.x < o) sd[threadIdx.x] += sd[threadIdx.x + o];
        __syncthreads();
    }
    if (threadIdx.x == 0) g_s[3] = sd[0];
}

// ---------------------------------------------------------------------------
// K6: fused MLP. Per 128-row tile:
//   x_i = c_i * v_b (regenerated, never hits HBM)
//   u = ssp(x); t = u @ W1^T; u = ssp(t); t2 = u @ W2^T; u = ssp(x + t2);
//   out = u @ Wo^T
// Activations stored TRANSPOSED in smem ([feature][row]) -> conflict-free
// float4 LDS on both operands; weights stay row-major (straight float4 copy).
// smem: xs_t 64KB + us_t 64KB + Ws 64KB = 192KB
// ---------------------------------------------------------------------------
__device__ __forceinline__ void mm128(const float* __restrict__ ut,
                                      const float* __restrict__ Ws,
                                      int r0, int f0, float acc[4][8]) {
#pragma unroll
    for (int k = 0; k < 4; k++)
#pragma unroll
        for (int c = 0; c < 8; c++) acc[k][c] = 0.f;

#pragma unroll 4
    for (int jb = 0; jb < 32; jb++) {
        int j = jb * 4;
        float4 u0 = *(const float4*)(ut + (j + 0) * 128 + r0);
        float4 u1 = *(const float4*)(ut + (j + 1) * 128 + r0);
        float4 u2 = *(const float4*)(ut + (j + 2) * 128 + r0);
        float4 u3 = *(const float4*)(ut + (j + 3) * 128 + r0);
#pragma unroll
        for (int c = 0; c < 8; c++) {
            float4 w = *(const float4*)(Ws + (f0 + c) * 128 + j);
            acc[0][c] += u0.x * w.x + u1.x * w.y + u2.x * w.z + u3.x * w.w;
            acc[1][c] += u0.y * w.x + u1.y * w.y + u2.y * w.z + u3.y * w.w;
            acc[2][c] += u0.z * w.x + u1.z * w.y + u2.z * w.z + u3.z * w.w;
            acc[3][c] += u0.w * w.x + u1.w * w.y + u2.w * w.z + u3.w * w.w;
        }
    }
}

__global__ void __launch_bounds__(512, 1)
k_mlp(const float* __restrict__ ef, const int* __restrict__ idx,
      const float* __restrict__ Wv, const float* __restrict__ W1,
      const float* __restrict__ W2, const float* __restrict__ Wo,
      float* __restrict__ out, int N) {
    extern __shared__ float sm[];
    float* xs = sm;           // [j][r] transposed x, 16384 floats
    float* us = sm + 16384;   // [j][r] transposed activation, 16384 floats
    float* Ws = sm + 32768;   // row-major weight [f][j], 16384 floats

    const int tid = threadIdx.x;
    const int row0 = blockIdx.x * 128;

    // phase 0: build x tile (c_i * v_b) + u = ssp(x), transposed layout
    {
        int r = tid & 127;
        int jg = tid >> 7;  // 0..3
        int i = row0 + r;
        float c = 0.f, e0 = 0.f, e1 = 0.f;
        if (i < N) {
            int b = idx[i];
            float v = ef[b];
            e0 = fmaxf(v, 0.f);
            e1 = fmaxf(-v, 0.f);
            c = g_ew[i] / (g_anorm[b] + 1e-8f * g_s[3]);
        }
#pragma unroll 8
        for (int j = jg * 32; j < jg * 32 + 32; j++) {
            float2 wv = ((const float2*)Wv)[j];
            float xval = c * (e0 * wv.x + e1 * wv.y);
            xs[j * 128 + r] = xval;
            us[j * 128 + r] = sspf(xval);
        }
    }
    // load W1
    for (int k2 = tid; k2 < 4096; k2 += 512) ((float4*)Ws)[k2] = ((const float4*)W1)[k2];
    __syncthreads();

    const int lane = tid & 31;
    const int wrp = tid >> 5;
    const int r0 = lane * 4;   // 4 rows per thread
    const int f0 = wrp * 8;    // 8 cols per thread
    float acc[4][8];

    // stage 1: t = u @ W1^T ; u = ssp(t)
    mm128(us, Ws, r0, f0, acc);
    __syncthreads();
#pragma unroll
    for (int c = 0; c < 8; c++) {
        float4 o;
        o.x = sspf(acc[0][c]); o.y = sspf(acc[1][c]);
        o.z = sspf(acc[2][c]); o.w = sspf(acc[3][c]);
        *(float4*)(us + (f0 + c) * 128 + r0) = o;
    }
    for (int k2 = tid; k2 < 4096; k2 += 512) ((float4*)Ws)[k2] = ((const float4*)W2)[k2];
    __syncthreads();

    // stage 2: t2 = u @ W2^T ; u = ssp(x + t2)
    mm128(us, Ws, r0, f0, acc);
    __syncthreads();
#pragma unroll
    for (int c = 0; c < 8; c++) {
        float4 xv = *(const float4*)(xs + (f0 + c) * 128 + r0);
        float4 o;
        o.x = sspf(xv.x + acc[0][c]); o.y = sspf(xv.y + acc[1][c]);
        o.z = sspf(xv.z + acc[2][c]); o.w = sspf(xv.w + acc[3][c]);
        *(float4*)(us + (f0 + c) * 128 + r0) = o;
    }
    for (int k2 = tid; k2 < 4096; k2 += 512) ((float4*)Ws)[k2] = ((const float4*)Wo)[k2];
    __syncthreads();

    // stage 3: out = u @ Wo^T -> gmem
    mm128(us, Ws, r0, f0, acc);
#pragma unroll
    for (int k = 0; k < 4; k++) {
        int i = row0 + r0 + k;
        if (i < N) {
            float4 o1 = make_float4(acc[k][0], acc[k][1], acc[k][2], acc[k][3]);
            float4 o2 = make_float4(acc[k][4], acc[k][5], acc[k][6], acc[k][7]);
            *(float4*)(out + (size_t)i * 128 + f0) = o1;
            *(float4*)(out + (size_t)i * 128 + f0 + 4) = o2;
        }
    }
}

// ---------------------------------------------------------------------------
extern "C" void kernel_launch(void* const* d_in, const int* in_sizes, int n_in,
                              void* d_out, int out_size) {
    const float* x   = (const float*)d_in[0];  // input_embedding [N,128]
    const float* ef  = (const float*)d_in[1];  // electronic_feature [B]
    const int*   idx = (const int*)d_in[2];    // idx_m [N]
    const float* Wq  = (const float*)d_in[3];  // [128,128]
    const float* bq  = (const float*)d_in[4];  // [128]
    const float* Wk  = (const float*)d_in[5];  // [128,2]
    const float* Wv  = (const float*)d_in[6];  // [128,2]
    const float* W1  = (const float*)d_in[7];  // [128,128]
    const float* W2  = (const float*)d_in[8];  // [128,128]
    const float* Wo  = (const float*)d_in[9];  // [128,128]
    float* out = (float*)d_out;

    int B = in_sizes[1];
    int N = in_sizes[2];

    k_prep<<<1, 128>>>(Wq, bq, Wk);

    int nb1 = (N + 7) / 8;
    k_w<<<nb1, 256>>>(x, ef, idx, N);
    k_max<<<1, 1024>>>(nb1);
    k_exp<<<(N + 255) / 256, 256>>>(N);
    k_anorm<<<(B + 7) / 8, 256>>>(idx, N, B);
    k_sum<<<1, 1024>>>(B);

    cudaFuncSetAttribute(k_mlp, cudaFuncAttributeMaxDynamicSharedMemorySize, 196608);
    k_mlp<<<(N + 127) / 128, 512, 196608>>>(ef, idx, Wv, W1, W2, Wo, out, N);
}